// round 13
// baseline (speedup 1.0000x reference)
#include <cuda_runtime.h>
#include <cuda_fp16.h>
#include <cstdint>

#define NTOK 2048
#define NBH  64
#define QSCALE 0.1803368801111204f   // log2(e) / 8
typedef uint32_t u32;
typedef uint16_t u16;

// single fp16 planes (Q pre-scaled by log2(e)/8 -> S-MMA yields log2-domain scores)
__device__ u16 g_qh[NBH * NTOK * 64];
__device__ u16 g_kh[NBH * NTOK * 64];
__device__ u16 g_vh[NBH * NTOK * 64];

__device__ __forceinline__ u32 smem_u32(const void* p) {
    u32 a; asm("{ .reg .u64 t; cvta.to.shared.u64 t, %1; cvt.u32.u64 %0, t; }" : "=r"(a) : "l"(p));
    return a;
}
__device__ __forceinline__ void ldsm4(u32 addr, u32 &r0, u32 &r1, u32 &r2, u32 &r3) {
    asm volatile("ldmatrix.sync.aligned.m8n8.x4.shared.b16 {%0,%1,%2,%3}, [%4];"
                 : "=r"(r0), "=r"(r1), "=r"(r2), "=r"(r3) : "r"(addr));
}
__device__ __forceinline__ void ldsm4t(u32 addr, u32 &r0, u32 &r1, u32 &r2, u32 &r3) {
    asm volatile("ldmatrix.sync.aligned.m8n8.x4.trans.shared.b16 {%0,%1,%2,%3}, [%4];"
                 : "=r"(r0), "=r"(r1), "=r"(r2), "=r"(r3) : "r"(addr));
}
__device__ __forceinline__ void mma_f16(float c[4], const u32 a[4], u32 b0, u32 b1) {
    asm volatile("mma.sync.aligned.m16n8k16.row.col.f32.f16.f16.f32 "
                 "{%0,%1,%2,%3},{%4,%5,%6,%7},{%8,%9},{%0,%1,%2,%3};"
                 : "+f"(c[0]), "+f"(c[1]), "+f"(c[2]), "+f"(c[3])
                 : "r"(a[0]), "r"(a[1]), "r"(a[2]), "r"(a[3]), "r"(b0), "r"(b1));
}
__device__ __forceinline__ u32 pack2h(float lo, float hi) {   // low half = lo
    u32 w; asm("cvt.rn.f16x2.f32 %0, %1, %2;" : "=r"(w) : "f"(hi), "f"(lo)); return w;
}
__device__ __forceinline__ u32 ex2x2(u32 s) {                 // 2^x on both halves
    u32 d; asm("ex2.approx.f16x2 %0, %1;" : "=r"(d) : "r"(s)); return d;
}
__device__ __forceinline__ void sts128(u32 a, uint4 v) {
    asm volatile("st.shared.v4.b32 [%0], {%1,%2,%3,%4};" :: "r"(a), "r"(v.x), "r"(v.y), "r"(v.z), "r"(v.w) : "memory");
}
__device__ __forceinline__ void cp16(u32 dst, const void* src) {
    asm volatile("cp.async.cg.shared.global [%0], [%1], 16;" :: "r"(dst), "l"(src) : "memory");
}
#define CP_COMMIT() asm volatile("cp.async.commit_group;" ::: "memory")
#define CP_WAIT0()  asm volatile("cp.async.wait_group 0;" ::: "memory")

// fragment address helpers (16B chunk XOR swizzle, 128B rows)
__device__ __forceinline__ u32 a_addr(u32 base, int row0, int chunk0, int lane) {
    int row = row0 + (lane & 15);
    int chunk = chunk0 + (lane >> 4);
    return base + row * 128 + ((chunk ^ (row & 7)) << 4);
}
__device__ __forceinline__ u32 b_addr(u32 base, int row0, int chunk0, int lane) {
    int row = row0 + (lane & 7);
    int chunk = chunk0 + (lane >> 3);
    return base + row * 128 + ((chunk ^ (row & 7)) << 4);
}

// exact fp16 hi/lo split of 8 floats
__device__ __forceinline__ void split8(const float4 f0, const float4 f1, uint4 &hv, uint4 &lv) {
    float a[8] = {f0.x, f0.y, f0.z, f0.w, f1.x, f1.y, f1.z, f1.w};
    float r[8];
#pragma unroll
    for (int e = 0; e < 8; e++) {
        __half hh = __float2half_rn(a[e]);
        r[e] = a[e] - __half2float(hh);
    }
    hv = make_uint4(pack2h(a[0],a[1]), pack2h(a[2],a[3]), pack2h(a[4],a[5]), pack2h(a[6],a[7]));
    lv = make_uint4(pack2h(r[0],r[1]), pack2h(r[2],r[3]), pack2h(r[4],r[5]), pack2h(r[6],r[7]));
}

// ---------------------------------------------------------------------------
// Kernel 1: QKV projection on tensor cores. Q,K: fp16 2-product (exact in x);
// V: 1-product. Per CTA: 128 rows x 192 outputs. smem 56K.
// ---------------------------------------------------------------------------
#define QKV_SMEM 57344
#define ATT_SMEM 73728   // Q 8K + 2 x (KH 16K + VH 16K)

__global__ void __launch_bounds__(256, 2) qkv_kernel(const float* __restrict__ x,
                                                     const float* __restrict__ W) {
    extern __shared__ char qsm[];
    const u32 sb = smem_u32(qsm);
    const u32 XH = sb, XL = sb + 16384, WH = sb + 32768;
    const int tid = threadIdx.x, lane = tid & 31, w = tid >> 5;
    const size_t row0 = (size_t)blockIdx.x * 128;

#pragma unroll
    for (int i = 0; i < 4; i++) {
        int cid = i * 256 + tid, r = cid >> 3, j = cid & 7;
        const float4* p = (const float4*)(x + (row0 + r) * 64 + j * 8);
        uint4 hv, lv; split8(p[0], p[1], hv, lv);
        u32 off = r * 128 + ((j ^ (r & 7)) << 4);
        sts128(XH + off, hv); sts128(XL + off, lv);
    }
#pragma unroll
    for (int i = 0; i < 6; i++) {
        int cid = i * 256 + tid, r = cid >> 3, j = cid & 7;
        const float4* p = (const float4*)(W + r * 64 + j * 8);
        float4 f0 = p[0], f1 = p[1];
        uint4 hv = make_uint4(pack2h(f0.x, f0.y), pack2h(f0.z, f0.w),
                              pack2h(f1.x, f1.y), pack2h(f1.z, f1.w));
        sts128(WH + r * 128 + ((j ^ (r & 7)) << 4), hv);
    }
    __syncthreads();

    u32 xh[4][4], xl[4][4];
#pragma unroll
    for (int ks = 0; ks < 4; ks++) {
        ldsm4(a_addr(XH, w * 16, 2 * ks, lane), xh[ks][0], xh[ks][1], xh[ks][2], xh[ks][3]);
        ldsm4(a_addr(XL, w * 16, 2 * ks, lane), xl[ks][0], xl[ks][1], xl[ks][2], xl[ks][3]);
    }

    const int g = w * 16 + (lane >> 2), t2 = (lane & 3) * 2;
#pragma unroll
    for (int nb = 0; nb < 24; nb += 2) {
        u32 bh0[8], bh1[8];
        ldsm4(b_addr(WH, nb * 8, 0, lane),       bh0[0], bh0[1], bh0[2], bh0[3]);
        ldsm4(b_addr(WH, nb * 8, 4, lane),       bh0[4], bh0[5], bh0[6], bh0[7]);
        ldsm4(b_addr(WH, (nb + 1) * 8, 0, lane), bh1[0], bh1[1], bh1[2], bh1[3]);
        ldsm4(b_addr(WH, (nb + 1) * 8, 4, lane), bh1[4], bh1[5], bh1[6], bh1[7]);

        float acc0[4] = {0.f,0.f,0.f,0.f}, acc1[4] = {0.f,0.f,0.f,0.f};
#pragma unroll
        for (int ks = 0; ks < 4; ks++) {
            mma_f16(acc0, xh[ks], bh0[2*ks], bh0[2*ks+1]);
            mma_f16(acc1, xh[ks], bh1[2*ks], bh1[2*ks+1]);
            if (nb < 16) {   // xl product only for Q,K outputs
                mma_f16(acc0, xl[ks], bh0[2*ks], bh0[2*ks+1]);
                mma_f16(acc1, xl[ks], bh1[2*ks], bh1[2*ks+1]);
            }
        }
#pragma unroll
        for (int q2 = 0; q2 < 2; q2++) {
            const float* ac = q2 ? acc1 : acc0;
            int d = (nb + q2) * 8 + t2;
            float sc = (d < 64) ? QSCALE : 1.f;
            u16* dst = (d < 64) ? g_qh : ((d < 128) ? g_kh : g_vh);
            int dd = d & 63;
            *(u32*)&dst[(row0 + g) * 64 + dd]     = pack2h(ac[0] * sc, ac[1] * sc);
            *(u32*)&dst[(row0 + g + 8) * 64 + dd] = pack2h(ac[2] * sc, ac[3] * sc);
        }
    }
}

// ---------------------------------------------------------------------------
// Kernel 2: fp16 HMMA flash attention, BM=64 + warp key-split (2048 CTAs ->
// 6.92 waves, tail waste 15.6% -> 1.2%). 8 warps = 4 row-groups x 2 key-half
// groups; O and l are purely additive (no-max softmax) -> one smem pair
// reduction at the end. l via ones-MMA (R11 form; R12 scalar path regressed).
// smem: Q 8K | buf b: KH 16K + VH 16K. Total 72K, 2 CTAs/SM.
// ---------------------------------------------------------------------------
__global__ void __launch_bounds__(256, 2) attn_kernel(float* __restrict__ out) {
    extern __shared__ char smem[];
    const u32 sb = smem_u32(smem);

    const int tid = threadIdx.x, lane = tid & 31, w = tid >> 5;
    const int mg = w & 3, ng = w >> 2;          // row-group, key-half
    const int bh = blockIdx.y, m0 = blockIdx.x * 64;
    const int b = bh >> 3, h = bh & 7;
    const u16* qg = g_qh + ((size_t)bh * NTOK + m0) * 64;
    const u16* kg = g_kh + (size_t)bh * NTOK * 64;
    const u16* vg = g_vh + (size_t)bh * NTOK * 64;

    // prologue: Q tile (512 chunks) + tile 0 K/V (2 x 1024 chunks)
#pragma unroll
    for (int i = 0; i < 2; i++) {
        int id = i * 256 + tid, r = id >> 3, j = id & 7;
        cp16(sb + r * 128 + ((j ^ (r & 7)) << 4), qg + r * 64 + j * 8);
    }
#pragma unroll
    for (int i = 0; i < 8; i++) {
        int pl = i >> 2, cid = (i & 3) * 256 + tid, r = cid >> 3, j = cid & 7;
        const u16* s4 = (pl == 0 ? kg : vg) + (size_t)r * 64 + j * 8;
        cp16(sb + 8192 + pl * 16384 + r * 128 + ((j ^ (r & 7)) << 4), s4);
    }
    CP_COMMIT();
    CP_WAIT0();
    __syncthreads();

    u32 qh[4][4];
#pragma unroll
    for (int ks = 0; ks < 4; ks++)
        ldsm4(a_addr(sb, mg * 16, 2 * ks, lane), qh[ks][0], qh[ks][1], qh[ks][2], qh[ks][3]);

    float o[8][4];
#pragma unroll
    for (int cb = 0; cb < 8; cb++)
#pragma unroll
        for (int e = 0; e < 4; e++) o[cb][e] = 0.f;
    float lacc[4] = {0.f, 0.f, 0.f, 0.f};
    const u32 ONES = 0x3C003C00u;

    for (int kt = 0; kt < 16; kt++) {
        const u32 KB = sb + 8192 + (kt & 1) * 32768;
        const u32 VB = KB + 16384;

        if (kt < 15) {
            int nb = (kt + 1) & 1;
            size_t off = (size_t)(kt + 1) * 128 * 64;
#pragma unroll
            for (int i = 0; i < 8; i++) {
                int pl = i >> 2, cid = (i & 3) * 256 + tid, r = cid >> 3, j = cid & 7;
                const u16* s4 = (pl == 0 ? kg : vg) + off + (size_t)r * 64 + j * 8;
                cp16(sb + 8192 + nb * 32768 + pl * 16384 + r * 128 + ((j ^ (r & 7)) << 4), s4);
            }
            CP_COMMIT();
        }

#pragma unroll
        for (int s = 0; s < 4; s++) {   // this warp's 16-key slices in its half
            const int kb = ng * 64 + s * 16;
            u32 kA[8], kB2[8], v[16];
            ldsm4(b_addr(KB, kb,     0, lane), kA[0], kA[1], kA[2], kA[3]);
            ldsm4(b_addr(KB, kb,     4, lane), kA[4], kA[5], kA[6], kA[7]);
            ldsm4(b_addr(KB, kb + 8, 0, lane), kB2[0], kB2[1], kB2[2], kB2[3]);
            ldsm4(b_addr(KB, kb + 8, 4, lane), kB2[4], kB2[5], kB2[6], kB2[7]);
            ldsm4t(a_addr(VB, kb, 0, lane), v[0],  v[1],  v[2],  v[3]);
            ldsm4t(a_addr(VB, kb, 2, lane), v[4],  v[5],  v[6],  v[7]);
            ldsm4t(a_addr(VB, kb, 4, lane), v[8],  v[9],  v[10], v[11]);
            ldsm4t(a_addr(VB, kb, 6, lane), v[12], v[13], v[14], v[15]);

            float s0[4] = {0.f,0.f,0.f,0.f}, s1[4] = {0.f,0.f,0.f,0.f};
#pragma unroll
            for (int ks = 0; ks < 4; ks++) {
                mma_f16(s0, qh[ks], kA[2*ks],  kA[2*ks+1]);
                mma_f16(s1, qh[ks], kB2[2*ks], kB2[2*ks+1]);
            }

            u32 a[4];
            a[0] = ex2x2(pack2h(s0[0], s0[1]));
            a[1] = ex2x2(pack2h(s0[2], s0[3]));
            a[2] = ex2x2(pack2h(s1[0], s1[1]));
            a[3] = ex2x2(pack2h(s1[2], s1[3]));
            mma_f16(lacc, a, ONES, ONES);

#pragma unroll
            for (int cp = 0; cp < 4; cp++) {
                mma_f16(o[2*cp],   a, v[4*cp],     v[4*cp + 1]);
                mma_f16(o[2*cp+1], a, v[4*cp + 2], v[4*cp + 3]);
            }
        }

        if (kt < 15) { CP_WAIT0(); __syncthreads(); }
    }

    // cross-warp reduction: key-half ng=1 publishes, ng=0 combines + stores
    __syncthreads();
    float* red = (float*)(smem + 8192);
    const int ridx = (mg * 32 + lane) * 34;
    if (ng == 1) {
#pragma unroll
        for (int cb = 0; cb < 8; cb++)
#pragma unroll
            for (int e = 0; e < 4; e++) red[ridx + cb * 4 + e] = o[cb][e];
        red[ridx + 32] = lacc[0];
        red[ridx + 33] = lacc[2];
    }
    __syncthreads();
    if (ng == 0) {
#pragma unroll
        for (int cb = 0; cb < 8; cb++)
#pragma unroll
            for (int e = 0; e < 4; e++) o[cb][e] += red[ridx + cb * 4 + e];
        float inv0 = 1.f / (lacc[0] + red[ridx + 32]);
        float inv1 = 1.f / (lacc[2] + red[ridx + 33]);

        int g = mg * 16 + (lane >> 2), t2 = (lane & 3) * 2;
        int n0 = m0 + g, n1 = n0 + 8;
#pragma unroll
        for (int cb = 0; cb < 8; cb++) {   // c = cb*8 + t2 -> hp = cb, jp = t2
            float* d0 = out + (((size_t)(b * 8 + cb) * NTOK + n0) << 6) + h * 8 + t2;
            float* d1 = out + (((size_t)(b * 8 + cb) * NTOK + n1) << 6) + h * 8 + t2;
            *(float2*)d0 = make_float2(o[cb][0] * inv0, o[cb][1] * inv0);
            *(float2*)d1 = make_float2(o[cb][2] * inv1, o[cb][3] * inv1);
        }
    }
}

// ---------------------------------------------------------------------------
extern "C" void kernel_launch(void* const* d_in, const int* in_sizes, int n_in,
                              void* d_out, int out_size) {
    const float* x = (const float*)d_in[0];   // [8,8,2048,64]
    const float* W = (const float*)d_in[1];   // [192,64]
    float* out = (float*)d_out;               // [8,8,2048,64]

    cudaFuncSetAttribute(qkv_kernel,  cudaFuncAttributeMaxDynamicSharedMemorySize, QKV_SMEM);
    cudaFuncSetAttribute(attn_kernel, cudaFuncAttributeMaxDynamicSharedMemorySize, ATT_SMEM);

    qkv_kernel<<<(NBH * NTOK) / 128, 256, QKV_SMEM>>>(x, W);
    attn_kernel<<<dim3(NTOK / 64, NBH), 256, ATT_SMEM>>>(out);
}

// round 14
// speedup vs baseline: 1.0871x; 1.0871x over previous
#include <cuda_runtime.h>
#include <cuda_fp16.h>
#include <cstdint>

#define NTOK 2048
#define NBH  64
#define QSCALE 0.1803368801111204f   // log2(e) / 8
typedef uint32_t u32;
typedef uint16_t u16;

// single fp16 planes (Q pre-scaled by log2(e)/8 -> S-MMA yields log2-domain scores)
__device__ u16 g_qh[NBH * NTOK * 64];
__device__ u16 g_kh[NBH * NTOK * 64];
__device__ u16 g_vh[NBH * NTOK * 64];

__device__ __forceinline__ u32 smem_u32(const void* p) {
    u32 a; asm("{ .reg .u64 t; cvta.to.shared.u64 t, %1; cvt.u32.u64 %0, t; }" : "=r"(a) : "l"(p));
    return a;
}
__device__ __forceinline__ void ldsm4(u32 addr, u32 &r0, u32 &r1, u32 &r2, u32 &r3) {
    asm volatile("ldmatrix.sync.aligned.m8n8.x4.shared.b16 {%0,%1,%2,%3}, [%4];"
                 : "=r"(r0), "=r"(r1), "=r"(r2), "=r"(r3) : "r"(addr));
}
__device__ __forceinline__ void ldsm4t(u32 addr, u32 &r0, u32 &r1, u32 &r2, u32 &r3) {
    asm volatile("ldmatrix.sync.aligned.m8n8.x4.trans.shared.b16 {%0,%1,%2,%3}, [%4];"
                 : "=r"(r0), "=r"(r1), "=r"(r2), "=r"(r3) : "r"(addr));
}
__device__ __forceinline__ void mma_f16(float c[4], const u32 a[4], u32 b0, u32 b1) {
    asm volatile("mma.sync.aligned.m16n8k16.row.col.f32.f16.f16.f32 "
                 "{%0,%1,%2,%3},{%4,%5,%6,%7},{%8,%9},{%0,%1,%2,%3};"
                 : "+f"(c[0]), "+f"(c[1]), "+f"(c[2]), "+f"(c[3])
                 : "r"(a[0]), "r"(a[1]), "r"(a[2]), "r"(a[3]), "r"(b0), "r"(b1));
}
__device__ __forceinline__ u32 pack2h(float lo, float hi) {   // low half = lo
    u32 w; asm("cvt.rn.f16x2.f32 %0, %1, %2;" : "=r"(w) : "f"(hi), "f"(lo)); return w;
}
__device__ __forceinline__ u32 ex2x2(u32 s) {                 // 2^x on both halves
    u32 d; asm("ex2.approx.f16x2 %0, %1;" : "=r"(d) : "r"(s)); return d;
}
__device__ __forceinline__ void sts128(u32 a, uint4 v) {
    asm volatile("st.shared.v4.b32 [%0], {%1,%2,%3,%4};" :: "r"(a), "r"(v.x), "r"(v.y), "r"(v.z), "r"(v.w) : "memory");
}
__device__ __forceinline__ void cp16(u32 dst, const void* src) {
    asm volatile("cp.async.cg.shared.global [%0], [%1], 16;" :: "r"(dst), "l"(src) : "memory");
}
#define CP_COMMIT() asm volatile("cp.async.commit_group;" ::: "memory")
#define CP_WAIT0()  asm volatile("cp.async.wait_group 0;" ::: "memory")

// fragment address helpers (16B chunk XOR swizzle, 128B rows)
__device__ __forceinline__ u32 a_addr(u32 base, int row0, int chunk0, int lane) {
    int row = row0 + (lane & 15);
    int chunk = chunk0 + (lane >> 4);
    return base + row * 128 + ((chunk ^ (row & 7)) << 4);
}
__device__ __forceinline__ u32 b_addr(u32 base, int row0, int chunk0, int lane) {
    int row = row0 + (lane & 7);
    int chunk = chunk0 + (lane >> 3);
    return base + row * 128 + ((chunk ^ (row & 7)) << 4);
}

// exact fp16 hi/lo split of 8 floats
__device__ __forceinline__ void split8(const float4 f0, const float4 f1, uint4 &hv, uint4 &lv) {
    float a[8] = {f0.x, f0.y, f0.z, f0.w, f1.x, f1.y, f1.z, f1.w};
    float r[8];
#pragma unroll
    for (int e = 0; e < 8; e++) {
        __half hh = __float2half_rn(a[e]);
        r[e] = a[e] - __half2float(hh);
    }
    hv = make_uint4(pack2h(a[0],a[1]), pack2h(a[2],a[3]), pack2h(a[4],a[5]), pack2h(a[6],a[7]));
    lv = make_uint4(pack2h(r[0],r[1]), pack2h(r[2],r[3]), pack2h(r[4],r[5]), pack2h(r[6],r[7]));
}

// ---------------------------------------------------------------------------
// Kernel 1: QKV projection on tensor cores (R12 winner). Q,K: fp16 2-product
// (exact in x); V: 1-product. Per CTA: 128 rows x 192 outputs. smem 56K.
// ---------------------------------------------------------------------------
#define QKV_SMEM 57344
#define ATT_SMEM 81920   // Q 16K + 2 x (KH 16K + VH 16K)

__global__ void __launch_bounds__(256, 2) qkv_kernel(const float* __restrict__ x,
                                                     const float* __restrict__ W) {
    extern __shared__ char qsm[];
    const u32 sb = smem_u32(qsm);
    const u32 XH = sb, XL = sb + 16384, WH = sb + 32768;
    const int tid = threadIdx.x, lane = tid & 31, w = tid >> 5;
    const size_t row0 = (size_t)blockIdx.x * 128;

#pragma unroll
    for (int i = 0; i < 4; i++) {
        int cid = i * 256 + tid, r = cid >> 3, j = cid & 7;
        const float4* p = (const float4*)(x + (row0 + r) * 64 + j * 8);
        uint4 hv, lv; split8(p[0], p[1], hv, lv);
        u32 off = r * 128 + ((j ^ (r & 7)) << 4);
        sts128(XH + off, hv); sts128(XL + off, lv);
    }
#pragma unroll
    for (int i = 0; i < 6; i++) {
        int cid = i * 256 + tid, r = cid >> 3, j = cid & 7;
        const float4* p = (const float4*)(W + r * 64 + j * 8);
        float4 f0 = p[0], f1 = p[1];
        uint4 hv = make_uint4(pack2h(f0.x, f0.y), pack2h(f0.z, f0.w),
                              pack2h(f1.x, f1.y), pack2h(f1.z, f1.w));
        sts128(WH + r * 128 + ((j ^ (r & 7)) << 4), hv);
    }
    __syncthreads();

    u32 xh[4][4], xl[4][4];
#pragma unroll
    for (int ks = 0; ks < 4; ks++) {
        ldsm4(a_addr(XH, w * 16, 2 * ks, lane), xh[ks][0], xh[ks][1], xh[ks][2], xh[ks][3]);
        ldsm4(a_addr(XL, w * 16, 2 * ks, lane), xl[ks][0], xl[ks][1], xl[ks][2], xl[ks][3]);
    }

    const int g = w * 16 + (lane >> 2), t2 = (lane & 3) * 2;
#pragma unroll
    for (int nb = 0; nb < 24; nb += 2) {
        u32 bh0[8], bh1[8];
        ldsm4(b_addr(WH, nb * 8, 0, lane),       bh0[0], bh0[1], bh0[2], bh0[3]);
        ldsm4(b_addr(WH, nb * 8, 4, lane),       bh0[4], bh0[5], bh0[6], bh0[7]);
        ldsm4(b_addr(WH, (nb + 1) * 8, 0, lane), bh1[0], bh1[1], bh1[2], bh1[3]);
        ldsm4(b_addr(WH, (nb + 1) * 8, 4, lane), bh1[4], bh1[5], bh1[6], bh1[7]);

        float acc0[4] = {0.f,0.f,0.f,0.f}, acc1[4] = {0.f,0.f,0.f,0.f};
#pragma unroll
        for (int ks = 0; ks < 4; ks++) {
            mma_f16(acc0, xh[ks], bh0[2*ks], bh0[2*ks+1]);
            mma_f16(acc1, xh[ks], bh1[2*ks], bh1[2*ks+1]);
            if (nb < 16) {   // xl product only for Q,K outputs (V: negligible)
                mma_f16(acc0, xl[ks], bh0[2*ks], bh0[2*ks+1]);
                mma_f16(acc1, xl[ks], bh1[2*ks], bh1[2*ks+1]);
            }
        }
#pragma unroll
        for (int q2 = 0; q2 < 2; q2++) {
            const float* ac = q2 ? acc1 : acc0;
            int d = (nb + q2) * 8 + t2;
            float sc = (d < 64) ? QSCALE : 1.f;
            u16* dst = (d < 64) ? g_qh : ((d < 128) ? g_kh : g_vh);
            int dd = d & 63;
            *(u32*)&dst[(row0 + g) * 64 + dd]     = pack2h(ac[0] * sc, ac[1] * sc);
            *(u32*)&dst[(row0 + g + 8) * 64 + dd] = pack2h(ac[2] * sc, ac[3] * sc);
        }
    }
}

// ---------------------------------------------------------------------------
// Kernel 2: fp16 HMMA flash attention (R11 winner, best measured: 159.7us).
// S in log2 domain (Q pre-scaled), p = ex2.approx.f16x2; l via ones-MMA.
// 256 thr / 8 warps; BM=128; BN=128 tiles double-buffered via cp.async.
// smem: Q 16K | buf b: KH 16K + VH 16K. Total 80K, 2 CTAs/SM.
// ---------------------------------------------------------------------------
__global__ void __launch_bounds__(256, 2) attn_kernel(float* __restrict__ out) {
    extern __shared__ char smem[];
    const u32 sb = smem_u32(smem);

    const int tid = threadIdx.x, lane = tid & 31, w = tid >> 5;
    const int bh = blockIdx.y, m0 = blockIdx.x * 128;
    const int b = bh >> 3, h = bh & 7;
    const u16* qg = g_qh + ((size_t)bh * NTOK + m0) * 64;
    const u16* kg = g_kh + (size_t)bh * NTOK * 64;
    const u16* vg = g_vh + (size_t)bh * NTOK * 64;

    // prologue: Q tile + tile 0 K/V via cp.async
#pragma unroll
    for (int i = 0; i < 4; i++) {
        int id = i * 256 + tid, r = id >> 3, j = id & 7;
        cp16(sb + r * 128 + ((j ^ (r & 7)) << 4), qg + r * 64 + j * 8);
    }
#pragma unroll
    for (int i = 0; i < 8; i++) {
        int pl = i >> 2, cid = (i & 3) * 256 + tid, r = cid >> 3, j = cid & 7;
        const u16* s4 = (pl == 0 ? kg : vg) + (size_t)r * 64 + j * 8;
        cp16(sb + 16384 + pl * 16384 + r * 128 + ((j ^ (r & 7)) << 4), s4);
    }
    CP_COMMIT();
    CP_WAIT0();
    __syncthreads();

    u32 qh[4][4];
#pragma unroll
    for (int ks = 0; ks < 4; ks++)
        ldsm4(a_addr(sb, w * 16, 2 * ks, lane), qh[ks][0], qh[ks][1], qh[ks][2], qh[ks][3]);

    float o[8][4];
#pragma unroll
    for (int cb = 0; cb < 8; cb++)
#pragma unroll
        for (int e = 0; e < 4; e++) o[cb][e] = 0.f;
    float lacc[4] = {0.f, 0.f, 0.f, 0.f};
    const u32 ONES = 0x3C003C00u;

    for (int kt = 0; kt < 16; kt++) {
        const u32 KB = sb + 16384 + (kt & 1) * 32768;
        const u32 VB = KB + 16384;

        if (kt < 15) {
            int nb = (kt + 1) & 1;
            size_t off = (size_t)(kt + 1) * 128 * 64;
#pragma unroll
            for (int i = 0; i < 8; i++) {
                int pl = i >> 2, cid = (i & 3) * 256 + tid, r = cid >> 3, j = cid & 7;
                const u16* s4 = (pl == 0 ? kg : vg) + off + (size_t)r * 64 + j * 8;
                cp16(sb + 16384 + nb * 32768 + pl * 16384 + r * 128 + ((j ^ (r & 7)) << 4), s4);
            }
            CP_COMMIT();
        }

#pragma unroll
        for (int s = 0; s < 8; s++) {   // 16-key slices
            u32 kA[8], kB2[8], v[16];
            ldsm4(b_addr(KB, (2*s)   * 8, 0, lane), kA[0], kA[1], kA[2], kA[3]);
            ldsm4(b_addr(KB, (2*s)   * 8, 4, lane), kA[4], kA[5], kA[6], kA[7]);
            ldsm4(b_addr(KB, (2*s+1) * 8, 0, lane), kB2[0], kB2[1], kB2[2], kB2[3]);
            ldsm4(b_addr(KB, (2*s+1) * 8, 4, lane), kB2[4], kB2[5], kB2[6], kB2[7]);
            ldsm4t(a_addr(VB, s * 16, 0, lane), v[0],  v[1],  v[2],  v[3]);
            ldsm4t(a_addr(VB, s * 16, 2, lane), v[4],  v[5],  v[6],  v[7]);
            ldsm4t(a_addr(VB, s * 16, 4, lane), v[8],  v[9],  v[10], v[11]);
            ldsm4t(a_addr(VB, s * 16, 6, lane), v[12], v[13], v[14], v[15]);

            float s0[4] = {0.f,0.f,0.f,0.f}, s1[4] = {0.f,0.f,0.f,0.f};
#pragma unroll
            for (int ks = 0; ks < 4; ks++) {
                mma_f16(s0, qh[ks], kA[2*ks],  kA[2*ks+1]);
                mma_f16(s1, qh[ks], kB2[2*ks], kB2[2*ks+1]);
            }

            // p = 2^s in fp16 pairs; l via ones-MMA
            u32 a[4];
            a[0] = ex2x2(pack2h(s0[0], s0[1]));
            a[1] = ex2x2(pack2h(s0[2], s0[3]));
            a[2] = ex2x2(pack2h(s1[0], s1[1]));
            a[3] = ex2x2(pack2h(s1[2], s1[3]));
            mma_f16(lacc, a, ONES, ONES);

#pragma unroll
            for (int cp = 0; cp < 4; cp++) {
                mma_f16(o[2*cp],   a, v[4*cp],     v[4*cp + 1]);
                mma_f16(o[2*cp+1], a, v[4*cp + 2], v[4*cp + 3]);
            }
        }

        if (kt < 15) { CP_WAIT0(); __syncthreads(); }
    }

    // normalize + head-mix store (l exact from ones-MMA)
    float inv0 = 1.f / lacc[0], inv1 = 1.f / lacc[2];
    int g = w * 16 + (lane >> 2), t2 = (lane & 3) * 2;
    int n0 = m0 + g, n1 = n0 + 8;
#pragma unroll
    for (int cb = 0; cb < 8; cb++) {   // c = cb*8 + t2 -> hp = cb, jp = t2
        float* d0 = out + (((size_t)(b * 8 + cb) * NTOK + n0) << 6) + h * 8 + t2;
        float* d1 = out + (((size_t)(b * 8 + cb) * NTOK + n1) << 6) + h * 8 + t2;
        *(float2*)d0 = make_float2(o[cb][0] * inv0, o[cb][1] * inv0);
        *(float2*)d1 = make_float2(o[cb][2] * inv1, o[cb][3] * inv1);
    }
}

// ---------------------------------------------------------------------------
extern "C" void kernel_launch(void* const* d_in, const int* in_sizes, int n_in,
                              void* d_out, int out_size) {
    const float* x = (const float*)d_in[0];   // [8,8,2048,64]
    const float* W = (const float*)d_in[1];   // [192,64]
    float* out = (float*)d_out;               // [8,8,2048,64]

    cudaFuncSetAttribute(qkv_kernel,  cudaFuncAttributeMaxDynamicSharedMemorySize, QKV_SMEM);
    cudaFuncSetAttribute(attn_kernel, cudaFuncAttributeMaxDynamicSharedMemorySize, ATT_SMEM);

    qkv_kernel<<<(NBH * NTOK) / 128, 256, QKV_SMEM>>>(x, W);
    attn_kernel<<<dim3(NTOK / 128, NBH), 256, ATT_SMEM>>>(out);
}